// round 1
// baseline (speedup 1.0000x reference)
#include <cuda_runtime.h>
#include <cuda_bf16.h>
#include <cfloat>

// Problem constants (fixed by the reference setup_inputs)
#define NN 2048
#define FF 64
#define KTOP 8
#define OUT_ROW (  (KTOP + 1) * FF )   // 9*64 = 576 floats per output node

// Scratch: per-feature candidate list sorted by x descending.
// pair.x = x value, pair.y = __int_as_float(original n index)
__device__ float2 g_sorted[FF * NN];   // 1 MB static device scratch (allowed)

// ---------------------------------------------------------------------------
// Kernel 1: for each feature f, sort (x[n][f], n) by value DESCENDING.
// One block per feature, bitonic sort in shared memory.
// ---------------------------------------------------------------------------
__global__ void sort_cols_kernel(const float* __restrict__ x) {
    __shared__ float sv[NN];
    __shared__ int   si[NN];
    const int f  = blockIdx.x;
    const int bs = blockDim.x;
    const int tid = threadIdx.x;

    for (int i = tid; i < NN; i += bs) {
        sv[i] = x[i * FF + f];
        si[i] = i;
    }
    __syncthreads();

    // Bitonic sort, descending
    for (int k = 2; k <= NN; k <<= 1) {
        for (int j = k >> 1; j > 0; j >>= 1) {
            for (int i = tid; i < NN; i += bs) {
                int ixj = i ^ j;
                if (ixj > i) {
                    bool up = ((i & k) == 0);   // descending overall
                    float a = sv[i], b = sv[ixj];
                    bool doswap = up ? (a < b) : (a > b);
                    if (doswap) {
                        sv[i] = b; sv[ixj] = a;
                        int t = si[i]; si[i] = si[ixj]; si[ixj] = t;
                    }
                }
            }
            __syncthreads();
        }
    }

    float2* dst = g_sorted + (size_t)f * NN;
    for (int i = tid; i < NN; i += bs) {
        dst[i] = make_float2(sv[i], __int_as_float(si[i]));
    }
}

// ---------------------------------------------------------------------------
// Kernel 2: pruned top-8 scan.
// One warp handles (feature f, 32 consecutive output nodes m).
// Lanes share the candidate list (uniform broadcast loads); adj[n][m] reads
// are fully coalesced across lanes. Exact early termination:
//   all remaining products v satisfy v <= max(x_i, 0) <= current 8th-largest.
// ---------------------------------------------------------------------------
__global__ void __launch_bounds__(256) topk_scan_kernel(
        const float* __restrict__ adj, float* __restrict__ out) {
    const int gtid = blockIdx.x * blockDim.x + threadIdx.x;
    const int warp = gtid >> 5;
    const int lane = threadIdx.x & 31;
    const int f  = warp >> 6;        // 64 m-groups per feature
    const int mg = warp & 63;
    const int m  = mg * 32 + lane;

    const float2* __restrict__ pairs = g_sorted + (size_t)f * NN;

    float arr[KTOP];
#pragma unroll
    for (int j = 0; j < KTOP; j++) arr[j] = -FLT_MAX;

    float2 p = __ldg(&pairs[0]);
    int i = 0;
    while (true) {
        // prefetch next candidate pair (uniform across warp)
        int inext = i + 1; if (inext > NN - 1) inext = NN - 1;
        float2 pn = __ldg(&pairs[inext]);

        const int   n = __float_as_int(p.y);
        const float a = __ldg(&adj[n * NN + m]);   // coalesced over lanes
        const float v = a * p.x;

        // Branchless sorted insert (no-op when v <= arr[7]); gate per-warp.
        if (__any_sync(0xffffffffu, v > arr[KTOP - 1])) {
            float keep = v;
#pragma unroll
            for (int j = 0; j < KTOP; j++) {
                float mx = fmaxf(arr[j], keep);
                keep     = fminf(arr[j], keep);
                arr[j]   = mx;
            }
        }

        // Remaining items have value <= max(p.x, 0). If that bound cannot
        // beat any lane's 8th-largest, the top-8 value sets are final.
        bool more = (fmaxf(p.x, 0.0f) > arr[KTOP - 1]);
        i++;
        if (i >= NN || !__any_sync(0xffffffffu, more)) break;
        p = pn;
    }

    // out[m, 1+j, f]
    float* o = out + (size_t)m * OUT_ROW + FF + f;
#pragma unroll
    for (int j = 0; j < KTOP; j++) o[j * FF] = arr[j];
}

// ---------------------------------------------------------------------------
// Kernel 3: out[m, 0, f] = x[m, f]
// ---------------------------------------------------------------------------
__global__ void copy_row0_kernel(const float* __restrict__ x,
                                 float* __restrict__ out) {
    int t = blockIdx.x * blockDim.x + threadIdx.x;
    if (t < NN * FF) {
        int m = t >> 6;       // /FF
        int f = t & (FF - 1);
        out[(size_t)m * OUT_ROW + f] = x[t];
    }
}

extern "C" void kernel_launch(void* const* d_in, const int* in_sizes, int n_in,
                              void* d_out, int out_size) {
    // Identify inputs by size (x: N*F, adj: N*N)
    const float* x   = (const float*)d_in[0];
    const float* adj = (const float*)d_in[1];
    if (in_sizes[0] == NN * NN) {   // swapped order safety
        adj = (const float*)d_in[0];
        x   = (const float*)d_in[1];
    }
    float* out = (float*)d_out;

    // 1) sort candidates per feature
    sort_cols_kernel<<<FF, 512>>>(x);

    // 2) pruned top-8 scan: 64 f * 64 m-groups = 4096 warps
    const int total_threads = FF * (NN / 32) * 32;   // 131072
    topk_scan_kernel<<<total_threads / 256, 256>>>(adj, out);

    // 3) k=0 slice copy
    copy_row0_kernel<<<(NN * FF + 255) / 256, 256>>>(x, out);
}

// round 2
// speedup vs baseline: 1.7654x; 1.7654x over previous
#include <cuda_runtime.h>
#include <cuda_bf16.h>
#include <cfloat>

// Problem constants (fixed by reference setup_inputs)
#define NN 2048
#define FF 64
#define KTOP 8
#define OUT_ROW ((KTOP + 1) * FF)   // 576 floats per output node

// Binning parameters: descending bins over value range.
#define NBINS 512
#define BIN_HI 4.25f
#define BIN_W  (8.5f / (float)NBINS)      // 0.016601563
#define BIN_INVW ((float)NBINS / 8.5f)

// Scratch: per-feature candidate list, grouped by descending value-bin.
// pair.x = x value, pair.y = __int_as_float(original n index)
__device__ float2 g_binned[FF * NN];   // 1 MB static device scratch

__device__ __forceinline__ int bin_of(float v) {
    int b = (int)((BIN_HI - v) * BIN_INVW);
    return max(0, min(NBINS - 1, b));
}

// Upper bound on the value of ANY candidate at position >= current one
// (same bin or later bins). Conservative eps covers float rounding.
__device__ __forceinline__ float remaining_bound(float v) {
    int b = bin_of(v);
    return (b == 0) ? FLT_MAX : (BIN_HI - (float)b * BIN_W + 1e-3f);
}

// ---------------------------------------------------------------------------
// Kernel 1: per-feature bucket binning (replaces full sort).
// One block per feature: smem histogram -> exclusive scan -> scatter.
// ---------------------------------------------------------------------------
__global__ void __launch_bounds__(256) bin_cols_kernel(const float* __restrict__ x) {
    __shared__ float sx[NN];          // 8 KB
    __shared__ int   cnt[NBINS];      // 2 KB
    __shared__ int   sa[NBINS];       // 2 KB
    __shared__ int   sb[NBINS];       // 2 KB
    __shared__ int   cursor[NBINS];   // 2 KB

    const int f   = blockIdx.x;
    const int tid = threadIdx.x;
    const int bs  = blockDim.x;       // 256

    for (int i = tid; i < NBINS; i += bs) cnt[i] = 0;
    __syncthreads();

    // Load column + histogram
    for (int i = tid; i < NN; i += bs) {
        float v = __ldg(&x[i * FF + f]);
        sx[i] = v;
        atomicAdd(&cnt[bin_of(v)], 1);
    }
    __syncthreads();

    // Inclusive scan of cnt (Hillis-Steele, double buffer, 9 steps)
    for (int i = tid; i < NBINS; i += bs) sa[i] = cnt[i];
    __syncthreads();
    int* src = sa; int* dst = sb;
    for (int d = 1; d < NBINS; d <<= 1) {
        for (int i = tid; i < NBINS; i += bs)
            dst[i] = src[i] + ((i >= d) ? src[i - d] : 0);
        __syncthreads();
        int* t = src; src = dst; dst = t;
    }
    // exclusive offsets
    for (int i = tid; i < NBINS; i += bs) cursor[i] = src[i] - cnt[i];
    __syncthreads();

    // Scatter (within-bin order arbitrary; top-k VALUES are order-invariant)
    float2* out = g_binned + (size_t)f * NN;
    for (int i = tid; i < NN; i += bs) {
        float v = sx[i];
        int pos = atomicAdd(&cursor[bin_of(v)], 1);
        out[pos] = make_float2(v, __int_as_float(i));
    }
}

// ---------------------------------------------------------------------------
// Kernel 2: pruned top-8 scan + k=0 slice copy.
// One warp per (feature f, 32 consecutive output nodes m).
// Candidate list loads are warp-uniform; adj[n][m] is coalesced over lanes.
// Exact early termination: remaining products v <= max(remaining_bound, 0).
// ---------------------------------------------------------------------------
__global__ void __launch_bounds__(256) topk_scan_kernel(
        const float* __restrict__ adj,
        const float* __restrict__ x,
        float* __restrict__ out) {
    const int gtid = blockIdx.x * blockDim.x + threadIdx.x;
    const int warp = gtid >> 5;
    const int lane = threadIdx.x & 31;
    const int f  = warp >> 6;        // 64 m-groups per feature
    const int mg = warp & 63;
    const int m  = mg * 32 + lane;

    const float2* __restrict__ pairs = g_binned + (size_t)f * NN;
    const float*  __restrict__ acol  = adj + m;

    float arr[KTOP];
#pragma unroll
    for (int j = 0; j < KTOP; j++) arr[j] = -FLT_MAX;

    float2 p = __ldg(&pairs[0]);
    float  a = __ldg(acol + (size_t)__float_as_int(p.y) * NN);
    int i = 0;
    while (true) {
        // Prefetch next candidate + its adj row (MLP=2 on the dependent chain)
        int inext = i + 1; if (inext > NN - 1) inext = NN - 1;
        float2 pn = __ldg(&pairs[inext]);
        float  an = __ldg(acol + (size_t)__float_as_int(pn.y) * NN);

        const float v = a * p.x;

        // Branchless sorted insert, gated warp-uniformly
        if (__any_sync(0xffffffffu, v > arr[KTOP - 1])) {
            float keep = v;
#pragma unroll
            for (int j = 0; j < KTOP; j++) {
                float mx = fmaxf(arr[j], keep);
                keep     = fminf(arr[j], keep);
                arr[j]   = mx;
            }
        }

        // Remaining candidates bounded by current bin's upper edge (>=0 via a>=0)
        bool more = (fmaxf(remaining_bound(p.x), 0.0f) > arr[KTOP - 1]);
        i++;
        if (i >= NN || !__any_sync(0xffffffffu, more)) break;
        p = pn; a = an;
    }

    // out[m, 1+j, f]
    float* o = out + (size_t)m * OUT_ROW + FF + f;
#pragma unroll
    for (int j = 0; j < KTOP; j++) o[j * FF] = arr[j];

    // k=0 slice: out[m, 0, f] = x[m, f]
    out[(size_t)m * OUT_ROW + f] = __ldg(&x[m * FF + f]);
}

extern "C" void kernel_launch(void* const* d_in, const int* in_sizes, int n_in,
                              void* d_out, int out_size) {
    const float* x   = (const float*)d_in[0];
    const float* adj = (const float*)d_in[1];
    if (in_sizes[0] == NN * NN) {   // swapped order safety
        adj = (const float*)d_in[0];
        x   = (const float*)d_in[1];
    }
    float* out = (float*)d_out;

    // 1) bucket-bin candidates per feature (descending bins)
    bin_cols_kernel<<<FF, 256>>>(x);

    // 2) pruned top-8 scan (+ row0 copy): 64 f * 64 m-groups = 4096 warps
    const int total_threads = FF * (NN / 32) * 32;   // 131072
    topk_scan_kernel<<<total_threads / 256, 256>>>(adj, x, out);
}

// round 3
// speedup vs baseline: 2.3750x; 1.3453x over previous
#include <cuda_runtime.h>
#include <cuda_bf16.h>
#include <cfloat>

// Problem constants (fixed by reference setup_inputs)
#define NN 2048
#define FF 64
#define KTOP 8
#define OUT_ROW ((KTOP + 1) * FF)   // 576 floats per output node

// Binning parameters: descending bins over value range.
#define NBINS 512
#define BIN_HI 4.25f
#define BIN_W  (8.5f / (float)NBINS)
#define BIN_INVW ((float)NBINS / 8.5f)

#define SSTAGE 512      // pairs staged in smem per block
#define BATCH 8

// Scratch: per-feature candidate list, grouped by descending value-bin.
__device__ float2 g_binned[FF * NN];   // 1 MB static device scratch

__device__ __forceinline__ int bin_of(float v) {
    int b = (int)((BIN_HI - v) * BIN_INVW);
    return max(0, min(NBINS - 1, b));
}

// Upper bound on value of ANY candidate at position >= current one.
__device__ __forceinline__ float remaining_bound(float v) {
    int b = bin_of(v);
    return (b == 0) ? FLT_MAX : (BIN_HI - (float)b * BIN_W + 1e-3f);
}

// ---------------------------------------------------------------------------
// Kernel 1: per-feature bucket binning.
// ---------------------------------------------------------------------------
__global__ void __launch_bounds__(256) bin_cols_kernel(const float* __restrict__ x) {
    __shared__ float sx[NN];
    __shared__ int   cnt[NBINS];
    __shared__ int   sa[NBINS];
    __shared__ int   sb[NBINS];
    __shared__ int   cursor[NBINS];

    const int f   = blockIdx.x;
    const int tid = threadIdx.x;
    const int bs  = blockDim.x;

    for (int i = tid; i < NBINS; i += bs) cnt[i] = 0;
    __syncthreads();

    for (int i = tid; i < NN; i += bs) {
        float v = __ldg(&x[i * FF + f]);
        sx[i] = v;
        atomicAdd(&cnt[bin_of(v)], 1);
    }
    __syncthreads();

    for (int i = tid; i < NBINS; i += bs) sa[i] = cnt[i];
    __syncthreads();
    int* src = sa; int* dst = sb;
    for (int d = 1; d < NBINS; d <<= 1) {
        for (int i = tid; i < NBINS; i += bs)
            dst[i] = src[i] + ((i >= d) ? src[i - d] : 0);
        __syncthreads();
        int* t = src; src = dst; dst = t;
    }
    for (int i = tid; i < NBINS; i += bs) cursor[i] = src[i] - cnt[i];
    __syncthreads();

    float2* out = g_binned + (size_t)f * NN;
    for (int i = tid; i < NN; i += bs) {
        float v = sx[i];
        int pos = atomicAdd(&cursor[bin_of(v)], 1);
        out[pos] = make_float2(v, __int_as_float(i));
    }
}

// ---------------------------------------------------------------------------
// Kernel 2: pruned top-8 scan, batched + pipelined, smem-staged candidates.
// One warp per (feature f, 32 consecutive output nodes m).
// All 8 warps of a block share f (warp=gtid>>5, f=warp>>6, 8 warps/block).
// ---------------------------------------------------------------------------
__global__ void __launch_bounds__(256) topk_scan_kernel(
        const float* __restrict__ adj,
        const float* __restrict__ x,
        float* __restrict__ out) {
    __shared__ float2 sp[SSTAGE];     // 4 KB

    const int gtid = blockIdx.x * blockDim.x + threadIdx.x;
    const int warp = gtid >> 5;
    const int lane = threadIdx.x & 31;
    const int f  = warp >> 6;
    const int mg = warp & 63;
    const int m  = mg * 32 + lane;

    const float2* __restrict__ pairs = g_binned + (size_t)f * NN;

    // Cooperative stage of first SSTAGE candidate pairs (block shares f)
    {
        const float4* src = (const float4*)pairs;
        float4* dst = (float4*)sp;
        for (int i = threadIdx.x; i < SSTAGE / 2; i += blockDim.x)
            dst[i] = __ldg(src + i);
    }
    __syncthreads();

    const float* __restrict__ acol = adj + m;

    float arr[KTOP];
#pragma unroll
    for (int j = 0; j < KTOP; j++) arr[j] = -FLT_MAX;

    // pair accessor: smem fast path, global overflow fallback
#define PAIR_AT(i) ((i) < SSTAGE ? sp[(i)] : __ldg(&pairs[(i)]))

    float aC[BATCH], aN[BATCH];

    // Prologue: issue adj loads for batch 0 (indices from smem, LDS-latency only)
#pragma unroll
    for (int c = 0; c < BATCH; c++) {
        float2 p = PAIR_AT(c);
        aC[c] = __ldg(acol + (size_t)__float_as_int(p.y) * NN);
    }

    int base = 0;
    while (true) {
        const int nbase = base + BATCH;

        // Prefetch next batch's adj values (8 independent LDGs in flight)
        if (nbase < NN) {
#pragma unroll
            for (int c = 0; c < BATCH; c++) {
                float2 p = PAIR_AT(nbase + c);
                aN[c] = __ldg(acol + (size_t)__float_as_int(p.y) * NN);
            }
        }

        // Process current batch
        float v[BATCH];
        float lastx = 0.0f;
#pragma unroll
        for (int c = 0; c < BATCH; c++) {
            float2 p = PAIR_AT(base + c);
            v[c] = aC[c] * p.x;
            if (c == BATCH - 1) lastx = p.x;
        }

        float vmax = fmaxf(fmaxf(fmaxf(v[0], v[1]), fmaxf(v[2], v[3])),
                           fmaxf(fmaxf(v[4], v[5]), fmaxf(v[6], v[7])));

        if (__any_sync(0xffffffffu, vmax > arr[KTOP - 1])) {
#pragma unroll
            for (int c = 0; c < BATCH; c++) {
                if (__any_sync(0xffffffffu, v[c] > arr[KTOP - 1])) {
                    float keep = v[c];
#pragma unroll
                    for (int j = 0; j < KTOP; j++) {
                        float mx = fmaxf(arr[j], keep);
                        keep     = fminf(arr[j], keep);
                        arr[j]   = mx;
                    }
                }
            }
        }

        // Remaining candidates bounded by batch-last bin's upper edge
        bool more = (fmaxf(remaining_bound(lastx), 0.0f) > arr[KTOP - 1]);
        base = nbase;
        if (base >= NN || !__any_sync(0xffffffffu, more)) break;

#pragma unroll
        for (int c = 0; c < BATCH; c++) aC[c] = aN[c];
    }
#undef PAIR_AT

    // out[m, 1+j, f]
    float* o = out + (size_t)m * OUT_ROW + FF + f;
#pragma unroll
    for (int j = 0; j < KTOP; j++) o[j * FF] = arr[j];

    // k=0 slice: out[m, 0, f] = x[m, f]
    out[(size_t)m * OUT_ROW + f] = __ldg(&x[m * FF + f]);
}

extern "C" void kernel_launch(void* const* d_in, const int* in_sizes, int n_in,
                              void* d_out, int out_size) {
    const float* x   = (const float*)d_in[0];
    const float* adj = (const float*)d_in[1];
    if (in_sizes[0] == NN * NN) {
        adj = (const float*)d_in[0];
        x   = (const float*)d_in[1];
    }
    float* out = (float*)d_out;

    bin_cols_kernel<<<FF, 256>>>(x);

    const int total_threads = FF * (NN / 32) * 32;   // 131072
    topk_scan_kernel<<<total_threads / 256, 256>>>(adj, x, out);
}